// round 9
// baseline (speedup 1.0000x reference)
#include <cuda_runtime.h>
#include <cuda_bf16.h>
#include <math.h>
#include <stdint.h>

#define BB 8
#define NN 256
#define KK 128
#define HH 32
#define EMB 768
#define FD 768

#define GAB_ELEMS   (BB*HH*NN*NN)      // 16777216
#define MEF_ELEMS   (BB*NN*EMB)        // 1572864

// scratch (no cudaMalloc allowed)
__device__ float g_sumef[BB * NN * KK];
__device__ int   g_pad[BB * NN];

// ---------------------------------------------------------------------------
// SMEM layout (bytes).
//   A[2] : ef chunk bf16-pairs [256 j][20]  (16 kpairs + 4 pad), hi/lo, x2 buf
//   B1   : w1^T bf16-pairs     [128 h][68]  (64 kpairs + 4 pad)
//   B2   : w2^T bf16-pairs     [ 32 m][68]
//   G    : gelu bf16-pairs     [256 j][68]  hi aliases A, lo aliases B1
//   CST  : C2 staging fp32     [256 j][37]  aliases G-hi
//   + sort/permutation/window arrays (dedicated, no aliasing)
// ---------------------------------------------------------------------------
#define AHI0   0         // 20480
#define ALO0   20480     // 20480
#define AHI1   40960     // 20480
#define ALO1   61440     // 20480 -> 81920
#define B1HIO  81920     // 34816 -> 116736
#define B1LOO  116736    // 34816 -> 151552
#define B2HIO  151552    // 8704  -> 160256
#define B2LOO  160256    // 8704  -> 168960
#define GHIO   0         // 69632 (over A bufs)
#define GLOO   81920     // 69632 (exactly over B1)
#define CSTO   0         // 37888 (over G-hi)
#define TSOF   168960    // 1024  : t[j] original order
#define KEEPO  169984    // 1024  : keep[j] original order
#define SPARTO 171008    // 8192 (2 x 512 x float2)
#define TSSO   179200    // 1024  : t sorted ascending
#define PJSO   180224    // 1024  : perm: sorted row -> original j
#define KEEPSO 181248    // 1024  : keep in sorted space
#define INVO   182272    // 1024  : inverse perm: original j -> sorted row
#define SLOO   183296    // 64    : per-subtile k-step lo
#define SHIO   183360    // 64    : per-subtile k-step hi
#define SMEM_TOTAL 183424

// ---------------------------------------------------------------------------
__device__ __forceinline__ uint32_t smem_u32(const void* p) {
    uint32_t a;
    asm("{ .reg .u64 t; cvta.to.shared.u64 t, %1; cvt.u32.u64 %0, t; }"
        : "=r"(a) : "l"(p));
    return a;
}

__device__ __forceinline__ void mma_bf16(float* c, uint32_t a0, uint32_t a1,
                                         uint32_t a2, uint32_t a3,
                                         uint32_t b0, uint32_t b1) {
    asm volatile(
        "mma.sync.aligned.m16n8k16.row.col.f32.bf16.bf16.f32 "
        "{%0,%1,%2,%3}, {%4,%5,%6,%7}, {%8,%9}, {%0,%1,%2,%3};"
        : "+f"(c[0]), "+f"(c[1]), "+f"(c[2]), "+f"(c[3])
        : "r"(a0), "r"(a1), "r"(a2), "r"(a3), "r"(b0), "r"(b1));
}

__device__ __forceinline__ void ldsm_x4(uint32_t& r0, uint32_t& r1,
                                        uint32_t& r2, uint32_t& r3,
                                        uint32_t addr) {
    asm volatile("ldmatrix.sync.aligned.m8n8.x4.shared.b16 {%0,%1,%2,%3}, [%4];"
                 : "=r"(r0), "=r"(r1), "=r"(r2), "=r"(r3) : "r"(addr));
}

// split e0,e1 into bf16 hi/lo pairs; packed reg = (elem k low 16, k+1 high)
__device__ __forceinline__ void splitpack(float e0, float e1,
                                          uint32_t& hi, uint32_t& lo) {
    __nv_bfloat16 h0 = __float2bfloat16_rn(e0);
    __nv_bfloat16 h1 = __float2bfloat16_rn(e1);
    float h0f = __bfloat162float(h0);
    float h1f = __bfloat162float(h1);
    __nv_bfloat16 l0 = __float2bfloat16_rn(e0 - h0f);
    __nv_bfloat16 l1 = __float2bfloat16_rn(e1 - h1f);
    hi = ((uint32_t)__bfloat16_as_ushort(h1) << 16) | __bfloat16_as_ushort(h0);
    lo = ((uint32_t)__bfloat16_as_ushort(l1) << 16) | __bfloat16_as_ushort(l0);
}

__device__ __forceinline__ float gelu_exact(float x) {
    return 0.5f * x * (1.0f + erff(x * 0.70710678118654752f));
}

// ---------------------------------------------------------------------------
__global__ void mask_kernel(const float* __restrict__ nf) {
    int bn = blockIdx.x;
    const float* p = nf + (size_t)bn * FD;
    int nz = 0;
    for (int q = threadIdx.x; q < FD; q += blockDim.x)
        nz |= (p[q] != 0.0f);
    int any = __syncthreads_or(nz);
    if (threadIdx.x == 0) g_pad[bn] = (any == 0) ? 1 : 0;
}

// ---------------------------------------------------------------------------
__global__ __launch_bounds__(512, 1)
void main_kernel(const float* __restrict__ pos,
                 const float* __restrict__ means,
                 const float* __restrict__ betas,
                 const float* __restrict__ w1,
                 const float* __restrict__ b1,
                 const float* __restrict__ w2,
                 const float* __restrict__ b2,
                 float* __restrict__ gab,
                 float* __restrict__ dpos)
{
    extern __shared__ char smem[];
    const uint32_t sbase = smem_u32(smem);
    uint32_t* Bhi  = (uint32_t*)(smem + B1HIO);
    uint32_t* Blo  = (uint32_t*)(smem + B1LOO);
    uint32_t* B2hi = (uint32_t*)(smem + B2HIO);
    uint32_t* B2lo = (uint32_t*)(smem + B2LOO);
    uint32_t* Ghi  = (uint32_t*)(smem + GHIO);
    uint32_t* Glo  = (uint32_t*)(smem + GLOO);
    float*    Cst  = (float*)(smem + CSTO);
    float*    ts   = (float*)(smem + TSOF);
    float*    keep = (float*)(smem + KEEPO);
    float2*   spart = (float2*)(smem + SPARTO);  // [2][512]
    float*    tss  = (float*)(smem + TSSO);
    int*      pjs  = (int*)(smem + PJSO);
    float*    keeps = (float*)(smem + KEEPSO);
    int*      invp = (int*)(smem + INVO);
    int*      s_slo = (int*)(smem + SLOO);
    int*      s_shi = (int*)(smem + SHIO);

    const int i    = blockIdx.x;
    const int b    = blockIdx.y;
    const int tid  = threadIdx.x;
    const int w    = tid >> 5;
    const int lane = tid & 31;
    const int g    = lane >> 2;   // fragment row group
    const int c4   = lane & 3;    // fragment col group

    // ldmatrix per-lane address components
    const int lmat = lane >> 3, lrow = lane & 7;
    const int rowA = lrow + 8 * (lmat & 1);          // A/G pattern
    const int kaddA = (lmat >> 1) * 4;
    const int rowB = lrow + 8 * (lmat >> 1);         // B pattern
    const int kaddB = (lmat & 1) * 4;

    // ---- B1 = w1^T as bf16 hi/lo pairs (64 kpairs, stride 68) ----
    {
        int h  = tid & 127;
        int kg = tid >> 7;                 // 0..3
#pragma unroll
        for (int q = 0; q < 16; q++) {
            int kp = kg * 16 + q;          // 0..63
            float v0 = w1[(2 * kp) * 128 + h];
            float v1 = w1[(2 * kp + 1) * 128 + h];
            uint32_t hi, lo;
            splitpack(v0, v1, hi, lo);
            Bhi[h * 68 + kp] = hi;
            Blo[h * 68 + kp] = lo;
        }
    }
    // ---- B2 = w2^T as bf16 hi/lo pairs (64 hpairs, stride 68) ----
    {
        int m  = tid & 31;
        int hg = tid >> 5;                 // 0..15
#pragma unroll
        for (int q = 0; q < 4; q++) {
            int hp = hg * 4 + q;           // 0..63
            float v0 = w2[(2 * hp) * 32 + m];
            float v1 = w2[(2 * hp + 1) * 32 + m];
            uint32_t hi, lo;
            splitpack(v0, v1, hi, lo);
            B2hi[m * 68 + hp] = hi;
            B2lo[m * 68 + hp] = lo;
        }
    }

    // ---- phase 0: dpos, t[j], keep[j] ----
    const float pix = pos[(b * NN + i) * 3 + 0];
    const float piy = pos[(b * NN + i) * 3 + 1];
    const float piz = pos[(b * NN + i) * 3 + 2];
    if (tid < NN) {
        int j = tid;
        float pjx = pos[(b * NN + j) * 3 + 0];
        float pjy = pos[(b * NN + j) * 3 + 1];
        float pjz = pos[(b * NN + j) * 3 + 2];
        float dx = pix - pjx, dy = piy - pjy, dz = piz - pjz;
        size_t dbase = (((size_t)(b * NN + i)) * NN + j) * 3;
        dpos[dbase + 0] = dx;
        dpos[dbase + 1] = dy;
        dpos[dbase + 2] = dz;
        float r = dx * dx + dy * dy + dz * dz;
        float d = (r > 0.0f) ? sqrtf(r) : 0.0f;
        ts[j] = expf(-d);               // ALPHA=1, CUT_LO=0
        keep[j] = g_pad[b * NN + j] ? 0.0f : 1.0f;
        tss[j] = ts[j];
        pjs[j] = j;
    }
    __syncthreads();

    // ---- bitonic sort (t ascending) on 256 (tss, pjs) pairs ----
    for (int ksz = 2; ksz <= 256; ksz <<= 1) {
        for (int jsz = ksz >> 1; jsz > 0; jsz >>= 1) {
            if (tid < 256) {
                int ixj = tid ^ jsz;
                if (ixj > tid) {
                    bool up = ((tid & ksz) == 0);
                    float a = tss[tid], c = tss[ixj];
                    bool swap = up ? (a > c) : (a < c);
                    if (swap) {
                        tss[tid] = c; tss[ixj] = a;
                        int pa = pjs[tid], pc = pjs[ixj];
                        pjs[tid] = pc; pjs[ixj] = pa;
                    }
                }
            }
            __syncthreads();
        }
    }

    // ---- per-16-row-subtile k-step windows; keeps/inv in sorted space ----
    if (tid < 16) {
        float m0 = means[0], m1 = means[1], be = betas[0];
        float delta = m1 - m0;
        float dmax = sqrtf(20.0f / be);      // cut where exp < ~2e-9
        float tmin = tss[tid * 16];
        float tmax = tss[tid * 16 + 15];
        int klo = (int)floorf((tmin - dmax - m0) / delta);
        int khi = (int)ceilf((tmax + dmax - m0) / delta);
        klo = klo < 0 ? 0 : (klo > 127 ? 127 : klo);
        khi = khi < klo ? klo : (khi > 127 ? 127 : khi);
        s_slo[tid] = klo >> 4;
        s_shi[tid] = khi >> 4;
    }
    if (tid < 256) {
        keeps[tid] = keep[pjs[tid]];
        invp[pjs[tid]] = tid;
    }

    // gen mapping: kp = tid&15 (k-pair in chunk), jg = tid>>4 (8 j each)
    const int gkp = tid & 15;
    const int gjg = tid >> 4;

    // ---- generate chunk 0 into buffer 0 (sorted row space) ----
    {
        uint32_t* Ah = (uint32_t*)(smem + AHI0);
        uint32_t* Al = (uint32_t*)(smem + ALO0);
        int k0 = 2 * gkp;
        float mk0 = means[k0], mk1 = means[k0 + 1];
        float bk0 = betas[k0], bk1 = betas[k0 + 1];
        float s0 = 0.0f, s1 = 0.0f;
#pragma unroll
        for (int q = 0; q < 8; q++) {
            int j = gjg * 8 + q;
            float t  = tss[j];
            float kj = keeps[j];
            float d0 = t - mk0, d1 = t - mk1;
            float e0 = expf(-bk0 * d0 * d0);
            float e1 = expf(-bk1 * d1 * d1);
            s0 += e0 * kj;  s1 += e1 * kj;
            uint32_t hi, lo;
            splitpack(e0, e1, hi, lo);
            Ah[j * 20 + gkp] = hi;
            Al[j * 20 + gkp] = lo;
        }
        spart[tid] = make_float2(s0, s1);
    }
    __syncthreads();

    // ================= GEMM1 accumulators ==================================
    const int wj = w & 3;    // j-tile: 64 sorted rows at wj*64
    const int wh = w >> 2;   // h-tile: 32 cols at wh*32

    // per-mi window (k-step units, 0..7); warp-wide union for B loads
    int slo_m[4], shi_m[4];
    int wlo = 8, whi = -1;
#pragma unroll
    for (int mi = 0; mi < 4; mi++) {
        int sub = wj * 4 + mi;
        slo_m[mi] = s_slo[sub];
        shi_m[mi] = s_shi[sub];
        wlo = min(wlo, slo_m[mi]);
        whi = max(whi, shi_m[mi]);
    }

    float acc[4][4][4];
#pragma unroll
    for (int mi = 0; mi < 4; mi++)
#pragma unroll
        for (int ni = 0; ni < 4; ni++)
#pragma unroll
            for (int q = 0; q < 4; q++) acc[mi][ni][q] = 0.0f;

    // ============ pipelined K-chunk loop (4 chunks of 32 k) ================
    for (int kc = 0; kc < 4; kc++) {
        const int buf = kc & 1;
        const uint32_t uAhi = sbase + (buf ? AHI1 : AHI0);
        const uint32_t uAlo = uAhi + 20480;

        // ---- MMA for chunk kc (2 k-steps of 16), window-gated ----
#pragma unroll
        for (int ks = 0; ks < 2; ks++) {
            int step = kc * 2 + ks;
            if (step < wlo || step > whi) continue;
            int kloc = ks * 8;                 // local k-pair base
            int kb   = kc * 16 + kloc;         // global k-pair for B1
            uint32_t bh[8], bl[8];
            ldsm_x4(bh[0], bh[1], bh[2], bh[3],
                sbase + B1HIO + (uint32_t)(((wh * 32 + rowB) * 68 + kb + kaddB) * 4));
            ldsm_x4(bh[4], bh[5], bh[6], bh[7],
                sbase + B1HIO + (uint32_t)(((wh * 32 + 16 + rowB) * 68 + kb + kaddB) * 4));
            ldsm_x4(bl[0], bl[1], bl[2], bl[3],
                sbase + B1LOO + (uint32_t)(((wh * 32 + rowB) * 68 + kb + kaddB) * 4));
            ldsm_x4(bl[4], bl[5], bl[6], bl[7],
                sbase + B1LOO + (uint32_t)(((wh * 32 + 16 + rowB) * 68 + kb + kaddB) * 4));
#pragma unroll
            for (int mi = 0; mi < 4; mi++) {
                if (step < slo_m[mi] || step > shi_m[mi]) continue;
                uint32_t aoff = (uint32_t)(((wj * 64 + mi * 16 + rowA) * 20
                                            + kloc + kaddA) * 4);
                uint32_t ah0, ah1, ah2, ah3, al0, al1, al2, al3;
                ldsm_x4(ah0, ah1, ah2, ah3, uAhi + aoff);
                ldsm_x4(al0, al1, al2, al3, uAlo + aoff);
#pragma unroll
                for (int ni = 0; ni < 4; ni++) {
                    mma_bf16(acc[mi][ni], ah0, ah1, ah2, ah3, bh[ni*2], bh[ni*2+1]);
                    mma_bf16(acc[mi][ni], al0, al1, al2, al3, bh[ni*2], bh[ni*2+1]);
                    mma_bf16(acc[mi][ni], ah0, ah1, ah2, ah3, bl[ni*2], bl[ni*2+1]);
                }
            }
        }

        // ---- fold masked j-sums of chunk kc (one warp; overlaps MMA) ----
        if (tid < 32) {
            int kp = tid >> 1, c = tid & 1;
            const float2* sp = spart + buf * 512;
            float s = 0.0f;
#pragma unroll
            for (int jg = 0; jg < 32; jg++) {
                float2 v = sp[jg * 16 + kp];
                s += c ? v.y : v.x;
            }
            g_sumef[((size_t)(b * NN + i)) * 128 + kc * 32 + tid] = s;
        }

        // ---- generate chunk kc+1 into other buffer (hides under MMA) ----
        if (kc < 3) {
            uint32_t* Ah = (uint32_t*)(smem + ((buf ^ 1) ? AHI1 : AHI0));
            uint32_t* Al = (uint32_t*)(smem + ((buf ^ 1) ? ALO1 : ALO0));
            int k0 = (kc + 1) * 32 + 2 * gkp;
            float mk0 = means[k0], mk1 = means[k0 + 1];
            float bk0 = betas[k0], bk1 = betas[k0 + 1];
            float s0 = 0.0f, s1 = 0.0f;
#pragma unroll
            for (int q = 0; q < 8; q++) {
                int j = gjg * 8 + q;
                float t  = tss[j];
                float kj = keeps[j];
                float d0 = t - mk0, d1 = t - mk1;
                float e0 = expf(-bk0 * d0 * d0);
                float e1 = expf(-bk1 * d1 * d1);
                s0 += e0 * kj;  s1 += e1 * kj;
                uint32_t hi, lo;
                splitpack(e0, e1, hi, lo);
                Ah[j * 20 + gkp] = hi;
                Al[j * 20 + gkp] = lo;
            }
            spart[(buf ^ 1) * 512 + tid] = make_float2(s0, s1);
        }
        __syncthreads();
    }

    // ---- epilogue1: +b1, exact GELU, split/pack into G (aliases A/B1) ----
    {
        float b1r0[4], b1r1[4];
#pragma unroll
        for (int ni = 0; ni < 4; ni++) {
            int h0 = wh * 32 + ni * 8 + c4 * 2;
            b1r0[ni] = b1[h0];
            b1r1[ni] = b1[h0 + 1];
        }
#pragma unroll
        for (int mi = 0; mi < 4; mi++) {
            int r0 = wj * 64 + mi * 16 + g;
            int r1 = r0 + 8;
#pragma unroll
            for (int ni = 0; ni < 4; ni++) {
                int hp = wh * 16 + ni * 4 + c4;
                float g00 = gelu_exact(acc[mi][ni][0] + b1r0[ni]);
                float g01 = gelu_exact(acc[mi][ni][1] + b1r1[ni]);
                float g10 = gelu_exact(acc[mi][ni][2] + b1r0[ni]);
                float g11 = gelu_exact(acc[mi][ni][3] + b1r1[ni]);
                uint32_t hi, lo;
                splitpack(g00, g01, hi, lo);
                Ghi[r0 * 68 + hp] = hi;  Glo[r0 * 68 + hp] = lo;
                splitpack(g10, g11, hi, lo);
                Ghi[r1 * 68 + hp] = hi;  Glo[r1 * 68 + hp] = lo;
            }
        }
    }
    __syncthreads();

    // ================= GEMM2: C2[256j][32m] = G @ w2 ========================
    float acc2[4][4];
#pragma unroll
    for (int ni = 0; ni < 4; ni++)
#pragma unroll
        for (int q = 0; q < 4; q++) acc2[ni][q] = 0.0f;

    const int jt = w * 16;
#pragma unroll
    for (int ks = 0; ks < 8; ks++) {
        int hp0 = ks * 8;
        uint32_t goff = (uint32_t)(((jt + rowA) * 68 + hp0 + kaddA) * 4);
        uint32_t gh0, gh1, gh2, gh3, gl0, gl1, gl2, gl3;
        ldsm_x4(gh0, gh1, gh2, gh3, sbase + GHIO + goff);
        ldsm_x4(gl0, gl1, gl2, gl3, sbase + GLOO + goff);
        uint32_t bh[8], bl[8];
        ldsm_x4(bh[0], bh[1], bh[2], bh[3],
            sbase + B2HIO + (uint32_t)(((rowB) * 68 + hp0 + kaddB) * 4));
        ldsm_x4(bh[4], bh[5], bh[6], bh[7],
            sbase + B2HIO + (uint32_t)(((16 + rowB) * 68 + hp0 + kaddB) * 4));
        ldsm_x4(bl[0], bl[1], bl[2], bl[3],
            sbase + B2LOO + (uint32_t)(((rowB) * 68 + hp0 + kaddB) * 4));
        ldsm_x4(bl[4], bl[5], bl[6], bl[7],
            sbase + B2LOO + (uint32_t)(((16 + rowB) * 68 + hp0 + kaddB) * 4));
#pragma unroll
        for (int ni = 0; ni < 4; ni++) {
            mma_bf16(acc2[ni], gh0, gh1, gh2, gh3, bh[ni*2], bh[ni*2+1]);
            mma_bf16(acc2[ni], gl0, gl1, gl2, gl3, bh[ni*2], bh[ni*2+1]);
            mma_bf16(acc2[ni], gh0, gh1, gh2, gh3, bl[ni*2], bl[ni*2+1]);
        }
    }

    __syncthreads();   // all G reads done; Cst may alias G-hi

    // ---- epilogue2: +b2 into staging (sorted row space) ----
#pragma unroll
    for (int ni = 0; ni < 4; ni++) {
        int m0 = ni * 8 + c4 * 2;
        float e0 = b2[m0], e1 = b2[m0 + 1];
        int r0 = jt + g, r1 = r0 + 8;
        Cst[r0 * 37 + m0]     = acc2[ni][0] + e0;
        Cst[r0 * 37 + m0 + 1] = acc2[ni][1] + e1;
        Cst[r1 * 37 + m0]     = acc2[ni][2] + e0;
        Cst[r1 * 37 + m0 + 1] = acc2[ni][3] + e1;
    }
    __syncthreads();

    // ---- coalesced gab stores: gab[b][m][i][j], gather via inverse perm ----
    {
        size_t base = (((size_t)b * HH) * NN + i) * NN;
#pragma unroll
        for (int it = 0; it < 16; it++) {
            int idx = it * 512 + tid;
            int m = idx >> 8;
            int j = idx & 255;
            int js = invp[j];
            float v = Cst[js * 37 + m];
            gab[base + (size_t)m * NN * NN + j] =
                (keep[j] == 0.0f) ? -1e20f : v;
        }
    }
}

// ---------------------------------------------------------------------------
// merge_edge_features = sum_ef @ ew + eb   ([2048,128] @ [128,768])
// ---------------------------------------------------------------------------
__global__ __launch_bounds__(256)
void merge_kernel(const float* __restrict__ ew,
                  const float* __restrict__ eb,
                  float* __restrict__ out)
{
    __shared__ float sef[16 * 128];
    const int r0  = blockIdx.x * 16;
    const int tid = threadIdx.x;

#pragma unroll
    for (int q = 0; q < 8; q++)
        sef[tid + 256 * q] = g_sumef[(size_t)r0 * 128 + tid + 256 * q];
    __syncthreads();

    float acc[3][16];
#pragma unroll
    for (int q = 0; q < 3; q++) {
        float e = eb[q * 256 + tid];
#pragma unroll
        for (int r = 0; r < 16; r++) acc[q][r] = e;
    }

    for (int k = 0; k < 128; k++) {
        float v0 = ew[(size_t)k * EMB + tid];
        float v1 = ew[(size_t)k * EMB + 256 + tid];
        float v2 = ew[(size_t)k * EMB + 512 + tid];
#pragma unroll
        for (int r = 0; r < 16; r++) {
            float s = sef[r * 128 + k];
            acc[0][r] = fmaf(s, v0, acc[0][r]);
            acc[1][r] = fmaf(s, v1, acc[1][r]);
            acc[2][r] = fmaf(s, v2, acc[2][r]);
        }
    }

#pragma unroll
    for (int r = 0; r < 16; r++)
#pragma unroll
        for (int q = 0; q < 3; q++)
            out[(size_t)(r0 + r) * EMB + q * 256 + tid] = acc[q][r];
}

// ---------------------------------------------------------------------------
extern "C" void kernel_launch(void* const* d_in, const int* in_sizes, int n_in,
                              void* d_out, int out_size) {
    const float* nf    = (const float*)d_in[0];
    const float* pos   = (const float*)d_in[1];
    const float* means = (const float*)d_in[2];
    const float* betas = (const float*)d_in[3];
    const float* w1    = (const float*)d_in[4];
    const float* b1    = (const float*)d_in[5];
    const float* w2    = (const float*)d_in[6];
    const float* b2    = (const float*)d_in[7];
    const float* ew    = (const float*)d_in[8];
    const float* eb    = (const float*)d_in[9];

    float* out  = (float*)d_out;
    float* gab  = out;
    float* mef  = out + GAB_ELEMS;
    float* dpos = out + GAB_ELEMS + MEF_ELEMS;

    cudaFuncSetAttribute(main_kernel,
                         cudaFuncAttributeMaxDynamicSharedMemorySize,
                         SMEM_TOTAL);

    mask_kernel<<<BB * NN, 128>>>(nf);

    dim3 grid(NN, BB);
    main_kernel<<<grid, 512, SMEM_TOTAL>>>(
        pos, means, betas, w1, b1, w2, b2, gab, dpos);

    merge_kernel<<<(BB * NN) / 16, 256>>>(ew, eb, mef);
}

// round 10
// speedup vs baseline: 1.2100x; 1.2100x over previous
#include <cuda_runtime.h>
#include <cuda_bf16.h>
#include <math.h>
#include <stdint.h>

#define BB 8
#define NN 256
#define KK 128
#define HH 32
#define EMB 768
#define FD 768

#define GAB_ELEMS   (BB*HH*NN*NN)      // 16777216
#define MEF_ELEMS   (BB*NN*EMB)        // 1572864

// scratch (no cudaMalloc allowed)
__device__ float g_sumef2[2 * BB * NN * KK];   // [jh][b*N+i][k]
__device__ int   g_pad[BB * NN];
// pre-packed mma B-fragments (bf16 hi/lo pairs), exact lane order
__device__ uint2 g_B1hi[4096], g_B1lo[4096];   // [(s*16+nb)*32 + lane]
__device__ uint2 g_B2hi[1024], g_B2lo[1024];   // [(s*4+nb)*32 + lane]

// ---------------------------------------------------------------------------
// SMEM layout (bytes), 256-thread block, 128 j rows:
//   A   : ef chunk bf16-pairs [128 j][20]  (16 kpairs + 4 pad) hi/lo
//   G   : gelu bf16-pairs     [128 j][68]  (64 hpairs + 4 pad) hi/lo
//   CST : C2 staging fp32     [128 j][37]
//   A aliases inside G-hi; CST aliases G-hi (all windows barrier-fenced)
// ---------------------------------------------------------------------------
#define GHIO   0         // 34816
#define GLOO   34816     // 34816 -> 69632
#define AHIO   0         // 10240 (inside G-hi, dead before G written)
#define ALOO   10240     // 10240 -> 20480
#define CSTO   0         // 18944 (over G-hi, after GEMM2)
#define TSOF   69632     // 512
#define KEEPO  70144     // 512
#define SPARTO 70656     // 2048 (256 x float2)
#define SMEM_TOTAL 72704

// ---------------------------------------------------------------------------
__device__ __forceinline__ uint32_t smem_u32(const void* p) {
    uint32_t a;
    asm("{ .reg .u64 t; cvta.to.shared.u64 t, %1; cvt.u32.u64 %0, t; }"
        : "=r"(a) : "l"(p));
    return a;
}

__device__ __forceinline__ void mma_bf16(float* c, uint32_t a0, uint32_t a1,
                                         uint32_t a2, uint32_t a3,
                                         uint32_t b0, uint32_t b1) {
    asm volatile(
        "mma.sync.aligned.m16n8k16.row.col.f32.bf16.bf16.f32 "
        "{%0,%1,%2,%3}, {%4,%5,%6,%7}, {%8,%9}, {%0,%1,%2,%3};"
        : "+f"(c[0]), "+f"(c[1]), "+f"(c[2]), "+f"(c[3])
        : "r"(a0), "r"(a1), "r"(a2), "r"(a3), "r"(b0), "r"(b1));
}

__device__ __forceinline__ void ldsm_x4(uint32_t& r0, uint32_t& r1,
                                        uint32_t& r2, uint32_t& r3,
                                        uint32_t addr) {
    asm volatile("ldmatrix.sync.aligned.m8n8.x4.shared.b16 {%0,%1,%2,%3}, [%4];"
                 : "=r"(r0), "=r"(r1), "=r"(r2), "=r"(r3) : "r"(addr));
}

// split e0,e1 into bf16 hi/lo pairs; packed reg = (elem k low 16, k+1 high)
__device__ __forceinline__ void splitpack(float e0, float e1,
                                          uint32_t& hi, uint32_t& lo) {
    __nv_bfloat16 h0 = __float2bfloat16_rn(e0);
    __nv_bfloat16 h1 = __float2bfloat16_rn(e1);
    float h0f = __bfloat162float(h0);
    float h1f = __bfloat162float(h1);
    __nv_bfloat16 l0 = __float2bfloat16_rn(e0 - h0f);
    __nv_bfloat16 l1 = __float2bfloat16_rn(e1 - h1f);
    hi = ((uint32_t)__bfloat16_as_ushort(h1) << 16) | __bfloat16_as_ushort(h0);
    lo = ((uint32_t)__bfloat16_as_ushort(l1) << 16) | __bfloat16_as_ushort(l0);
}

__device__ __forceinline__ float gelu_exact(float x) {
    return 0.5f * x * (1.0f + erff(x * 0.70710678118654752f));
}

// ---------------------------------------------------------------------------
__global__ void mask_kernel(const float* __restrict__ nf) {
    int bn = blockIdx.x;
    const float* p = nf + (size_t)bn * FD;
    int nz = 0;
    for (int q = threadIdx.x; q < FD; q += blockDim.x)
        nz |= (p[q] != 0.0f);
    int any = __syncthreads_or(nz);
    if (threadIdx.x == 0) g_pad[bn] = (any == 0) ? 1 : 0;
}

// ---------------------------------------------------------------------------
// pack w1^T / w2^T into mma B-fragment order:
//   B1: for k-step s(0..7), n-block nb(0..15), lane l:
//       n = nb*8 + l/4, kp = s*8 + (l&3); b0 = pair(kp), b1 = pair(kp+4)
//   B2: same with nb(0..3), hp over hidden dim
// ---------------------------------------------------------------------------
__global__ void prep_kernel(const float* __restrict__ w1,
                            const float* __restrict__ w2) {
    int t = blockIdx.x * 256 + threadIdx.x;     // grid 16 x 256 = 4096
    {
        int idx = t;
        int s  = idx >> 9;
        int nb = (idx >> 5) & 15;
        int l  = idx & 31;
        int h  = nb * 8 + (l >> 2);
        int kp = s * 8 + (l & 3);
        float v0 = w1[(2 * kp) * 128 + h];
        float v1 = w1[(2 * kp + 1) * 128 + h];
        float v2 = w1[(2 * (kp + 4)) * 128 + h];
        float v3 = w1[(2 * (kp + 4) + 1) * 128 + h];
        uint32_t h0, l0, h1, l1;
        splitpack(v0, v1, h0, l0);
        splitpack(v2, v3, h1, l1);
        g_B1hi[idx] = make_uint2(h0, h1);
        g_B1lo[idx] = make_uint2(l0, l1);
    }
    if (t < 1024) {
        int idx = t;
        int s  = idx >> 7;
        int nb = (idx >> 5) & 3;
        int l  = idx & 31;
        int m  = nb * 8 + (l >> 2);
        int hp = s * 8 + (l & 3);
        float v0 = w2[(2 * hp) * 32 + m];
        float v1 = w2[(2 * hp + 1) * 32 + m];
        float v2 = w2[(2 * (hp + 4)) * 32 + m];
        float v3 = w2[(2 * (hp + 4) + 1) * 32 + m];
        uint32_t h0, l0, h1, l1;
        splitpack(v0, v1, h0, l0);
        splitpack(v2, v3, h1, l1);
        g_B2hi[idx] = make_uint2(h0, h1);
        g_B2lo[idx] = make_uint2(l0, l1);
    }
}

// ---------------------------------------------------------------------------
// main: one block per (i, b, jhalf); 256 threads; occupancy 2
// ---------------------------------------------------------------------------
__global__ __launch_bounds__(256, 2)
void main_kernel(const float* __restrict__ pos,
                 const float* __restrict__ means,
                 const float* __restrict__ betas,
                 const float* __restrict__ b1,
                 const float* __restrict__ b2,
                 float* __restrict__ gab,
                 float* __restrict__ dpos)
{
    extern __shared__ char smem[];
    const uint32_t sbase = smem_u32(smem);
    uint32_t* Ahi  = (uint32_t*)(smem + AHIO);
    uint32_t* Alo  = (uint32_t*)(smem + ALOO);
    uint32_t* Ghi  = (uint32_t*)(smem + GHIO);
    uint32_t* Glo  = (uint32_t*)(smem + GLOO);
    float*    Cst  = (float*)(smem + CSTO);
    float*    ts   = (float*)(smem + TSOF);
    float*    keep = (float*)(smem + KEEPO);
    float2*   spart = (float2*)(smem + SPARTO);

    const int i    = blockIdx.x;
    const int b    = blockIdx.y;
    const int jh   = blockIdx.z;
    const int tid  = threadIdx.x;
    const int w    = tid >> 5;          // 0..7
    const int lane = tid & 31;
    const int g    = lane >> 2;
    const int c4   = lane & 3;

    // ldmatrix per-lane address components (A / G operand pattern)
    const int lmat = lane >> 3, lrow = lane & 7;
    const int rowA = lrow + 8 * (lmat & 1);
    const int kaddA = (lmat >> 1) * 4;

    // ---- phase 0: dpos, t[jl], keep[jl] for this half's 128 rows ----
    const float pix = pos[(b * NN + i) * 3 + 0];
    const float piy = pos[(b * NN + i) * 3 + 1];
    const float piz = pos[(b * NN + i) * 3 + 2];
    if (tid < 128) {
        int jl = tid;
        int j  = jh * 128 + jl;
        float pjx = pos[(b * NN + j) * 3 + 0];
        float pjy = pos[(b * NN + j) * 3 + 1];
        float pjz = pos[(b * NN + j) * 3 + 2];
        float dx = pix - pjx, dy = piy - pjy, dz = piz - pjz;
        size_t dbase = (((size_t)(b * NN + i)) * NN + j) * 3;
        dpos[dbase + 0] = dx;
        dpos[dbase + 1] = dy;
        dpos[dbase + 2] = dz;
        float r = dx * dx + dy * dy + dz * dz;
        float d = (r > 0.0f) ? sqrtf(r) : 0.0f;
        ts[jl] = expf(-d);              // ALPHA=1, CUT_LO=0
        keep[jl] = g_pad[b * NN + j] ? 0.0f : 1.0f;
    }
    __syncthreads();

    // ================= GEMM1: C1[128j x 128h] = ef @ w1 ====================
    const int wj = w & 1;    // 64 rows at wj*64
    const int wh = w >> 1;   // 32 cols at wh*32
    const int gkp = tid & 15;
    const int gjg = tid >> 4;

    float acc[4][4][4];
#pragma unroll
    for (int mi = 0; mi < 4; mi++)
#pragma unroll
        for (int ni = 0; ni < 4; ni++)
#pragma unroll
            for (int q = 0; q < 4; q++) acc[mi][ni][q] = 0.0f;

    for (int kc = 0; kc < 4; kc++) {
        // ---- generate A chunk [128 j][32 k] + masked partial sums ----
        {
            int k0 = kc * 32 + 2 * gkp;
            float mk0 = means[k0], mk1 = means[k0 + 1];
            float bk0 = betas[k0], bk1 = betas[k0 + 1];
            float s0 = 0.0f, s1 = 0.0f;
#pragma unroll
            for (int q = 0; q < 8; q++) {
                int jl = gjg * 8 + q;
                float t  = ts[jl];
                float kj = keep[jl];
                float d0 = t - mk0, d1 = t - mk1;
                float e0 = expf(-bk0 * d0 * d0);
                float e1 = expf(-bk1 * d1 * d1);
                s0 += e0 * kj;  s1 += e1 * kj;
                uint32_t hi, lo;
                splitpack(e0, e1, hi, lo);
                Ahi[jl * 20 + gkp] = hi;
                Alo[jl * 20 + gkp] = lo;
            }
            spart[tid] = make_float2(s0, s1);
        }
        __syncthreads();

        // ---- fold this half's masked j-sums (warp 0; overlaps MMA) ----
        if (tid < 32) {
            int kp = tid >> 1, c = tid & 1;
            float s = 0.0f;
#pragma unroll
            for (int jg = 0; jg < 16; jg++) {
                float2 v = spart[jg * 16 + kp];
                s += c ? v.y : v.x;
            }
            g_sumef2[(size_t)jh * (BB * NN * KK)
                     + ((size_t)(b * NN + i)) * 128 + kc * 32 + tid] = s;
        }

        // ---- MMA: 2 k-steps of 16; B frags streamed from L2 ----
#pragma unroll
        for (int ks = 0; ks < 2; ks++) {
            int s = kc * 2 + ks;
            uint2 bh[4], bl[4];
#pragma unroll
            for (int ni = 0; ni < 4; ni++) {
                int idx = ((s * 16 + wh * 4 + ni) * 32) + lane;
                bh[ni] = g_B1hi[idx];
                bl[ni] = g_B1lo[idx];
            }
            int kloc = ks * 8;
#pragma unroll
            for (int mi = 0; mi < 4; mi++) {
                uint32_t aoff = (uint32_t)(((wj * 64 + mi * 16 + rowA) * 20
                                            + kloc + kaddA) * 4);
                uint32_t ah0, ah1, ah2, ah3, al0, al1, al2, al3;
                ldsm_x4(ah0, ah1, ah2, ah3, sbase + AHIO + aoff);
                ldsm_x4(al0, al1, al2, al3, sbase + ALOO + aoff);
#pragma unroll
                for (int ni = 0; ni < 4; ni++) {
                    mma_bf16(acc[mi][ni], ah0, ah1, ah2, ah3, bh[ni].x, bh[ni].y);
                    mma_bf16(acc[mi][ni], al0, al1, al2, al3, bh[ni].x, bh[ni].y);
                    mma_bf16(acc[mi][ni], ah0, ah1, ah2, ah3, bl[ni].x, bl[ni].y);
                }
            }
        }
        __syncthreads();   // A consumed; next gen may overwrite
    }

    // ---- epilogue1: +b1, exact GELU, split/pack into G (aliases A) ----
    {
        float b1r0[4], b1r1[4];
#pragma unroll
        for (int ni = 0; ni < 4; ni++) {
            int h0 = wh * 32 + ni * 8 + c4 * 2;
            b1r0[ni] = b1[h0];
            b1r1[ni] = b1[h0 + 1];
        }
#pragma unroll
        for (int mi = 0; mi < 4; mi++) {
            int r0 = wj * 64 + mi * 16 + g;
            int r1 = r0 + 8;
#pragma unroll
            for (int ni = 0; ni < 4; ni++) {
                int hp = wh * 16 + ni * 4 + c4;
                float g00 = gelu_exact(acc[mi][ni][0] + b1r0[ni]);
                float g01 = gelu_exact(acc[mi][ni][1] + b1r1[ni]);
                float g10 = gelu_exact(acc[mi][ni][2] + b1r0[ni]);
                float g11 = gelu_exact(acc[mi][ni][3] + b1r1[ni]);
                uint32_t hi, lo;
                splitpack(g00, g01, hi, lo);
                Ghi[r0 * 68 + hp] = hi;  Glo[r0 * 68 + hp] = lo;
                splitpack(g10, g11, hi, lo);
                Ghi[r1 * 68 + hp] = hi;  Glo[r1 * 68 + hp] = lo;
            }
        }
    }
    __syncthreads();

    // ================= GEMM2: C2[128j x 32m] = G @ w2 ======================
    float acc2[4][4];
#pragma unroll
    for (int ni = 0; ni < 4; ni++)
#pragma unroll
        for (int q = 0; q < 4; q++) acc2[ni][q] = 0.0f;

    const int jt = w * 16;
#pragma unroll
    for (int s = 0; s < 8; s++) {
        uint32_t goff = (uint32_t)(((jt + rowA) * 68 + s * 8 + kaddA) * 4);
        uint32_t gh0, gh1, gh2, gh3, gl0, gl1, gl2, gl3;
        ldsm_x4(gh0, gh1, gh2, gh3, sbase + GHIO + goff);
        ldsm_x4(gl0, gl1, gl2, gl3, sbase + GLOO + goff);
        uint2 bh[4], bl[4];
#pragma unroll
        for (int ni = 0; ni < 4; ni++) {
            int idx = ((s * 4 + ni) * 32) + lane;
            bh[ni] = g_B2hi[idx];
            bl[ni] = g_B2lo[idx];
        }
#pragma unroll
        for (int ni = 0; ni < 4; ni++) {
            mma_bf16(acc2[ni], gh0, gh1, gh2, gh3, bh[ni].x, bh[ni].y);
            mma_bf16(acc2[ni], gl0, gl1, gl2, gl3, bh[ni].x, bh[ni].y);
            mma_bf16(acc2[ni], gh0, gh1, gh2, gh3, bl[ni].x, bl[ni].y);
        }
    }
    __syncthreads();   // G consumed; Cst may alias

    // ---- epilogue2: +b2 into staging ----
#pragma unroll
    for (int ni = 0; ni < 4; ni++) {
        int m0 = ni * 8 + c4 * 2;
        float e0 = b2[m0], e1 = b2[m0 + 1];
        int r0 = jt + g, r1 = r0 + 8;
        Cst[r0 * 37 + m0]     = acc2[ni][0] + e0;
        Cst[r0 * 37 + m0 + 1] = acc2[ni][1] + e1;
        Cst[r1 * 37 + m0]     = acc2[ni][2] + e0;
        Cst[r1 * 37 + m0 + 1] = acc2[ni][3] + e1;
    }
    __syncthreads();

    // ---- coalesced gab stores: gab[b][m][i][jh*128 + jl] ----
    {
#pragma unroll
        for (int it = 0; it < 16; it++) {
            int idx = it * 256 + tid;
            int m  = idx >> 7;
            int jl = idx & 127;
            int j  = jh * 128 + jl;
            float v = Cst[jl * 37 + m];
            gab[(((size_t)(b * HH + m)) * NN + i) * NN + j] =
                (keep[jl] == 0.0f) ? -1e20f : v;
        }
    }
}

// ---------------------------------------------------------------------------
// merge_edge_features = (sum over both halves) @ ew + eb
// ---------------------------------------------------------------------------
__global__ __launch_bounds__(256)
void merge_kernel(const float* __restrict__ ew,
                  const float* __restrict__ eb,
                  float* __restrict__ out)
{
    __shared__ float sef[16 * 128];
    const int r0  = blockIdx.x * 16;
    const int tid = threadIdx.x;

#pragma unroll
    for (int q = 0; q < 8; q++) {
        size_t off = (size_t)r0 * 128 + tid + 256 * q;
        sef[tid + 256 * q] = g_sumef2[off] + g_sumef2[(size_t)(BB*NN*KK) + off];
    }
    __syncthreads();

    float acc[3][16];
#pragma unroll
    for (int q = 0; q < 3; q++) {
        float e = eb[q * 256 + tid];
#pragma unroll
        for (int r = 0; r < 16; r++) acc[q][r] = e;
    }

    for (int k = 0; k < 128; k++) {
        float v0 = ew[(size_t)k * EMB + tid];
        float v1 = ew[(size_t)k * EMB + 256 + tid];
        float v2 = ew[(size_t)k * EMB + 512 + tid];
#pragma unroll
        for (int r = 0; r < 16; r++) {
            float s = sef[r * 128 + k];
            acc[0][r] = fmaf(s, v0, acc[0][r]);
            acc[1][r] = fmaf(s, v1, acc[1][r]);
            acc[2][r] = fmaf(s, v2, acc[2][r]);
        }
    }

#pragma unroll
    for (int r = 0; r < 16; r++)
#pragma unroll
        for (int q = 0; q < 3; q++)
            out[(size_t)(r0 + r) * EMB + q * 256 + tid] = acc[q][r];
}

// ---------------------------------------------------------------------------
extern "C" void kernel_launch(void* const* d_in, const int* in_sizes, int n_in,
                              void* d_out, int out_size) {
    const float* nf    = (const float*)d_in[0];
    const float* pos   = (const float*)d_in[1];
    const float* means = (const float*)d_in[2];
    const float* betas = (const float*)d_in[3];
    const float* w1    = (const float*)d_in[4];
    const float* b1    = (const float*)d_in[5];
    const float* w2    = (const float*)d_in[6];
    const float* b2    = (const float*)d_in[7];
    const float* ew    = (const float*)d_in[8];
    const float* eb    = (const float*)d_in[9];

    float* out  = (float*)d_out;
    float* gab  = out;
    float* mef  = out + GAB_ELEMS;
    float* dpos = out + GAB_ELEMS + MEF_ELEMS;

    cudaFuncSetAttribute(main_kernel,
                         cudaFuncAttributeMaxDynamicSharedMemorySize,
                         SMEM_TOTAL);

    prep_kernel<<<16, 256>>>(w1, w2);
    mask_kernel<<<BB * NN, 128>>>(nf);

    dim3 grid(NN, BB, 2);
    main_kernel<<<grid, 256, SMEM_TOTAL>>>(
        pos, means, betas, b1, b2, gab, dpos);

    merge_kernel<<<(BB * NN) / 16, 256>>>(ew, eb, mef);
}

// round 12
// speedup vs baseline: 1.3355x; 1.1037x over previous
#include <cuda_runtime.h>
#include <cuda_bf16.h>
#include <math.h>
#include <stdint.h>

#define BB 8
#define NN 256
#define KK 128
#define HH 32
#define EMB 768
#define FD 768

#define GAB_ELEMS   (BB*HH*NN*NN)      // 16777216
#define MEF_ELEMS   (BB*NN*EMB)        // 1572864

// scratch (no cudaMalloc allowed)
__device__ float g_sumef2[2 * BB * NN * KK];   // [jh][b*N+i][k]
__device__ int   g_pad[BB * NN];
// pre-packed mma B-fragments (bf16 hi/lo pairs), exact lane order
__device__ uint2 g_B1hi[4096], g_B1lo[4096];   // [(s*16+nb)*32 + lane]
__device__ uint2 g_B2hi[1024], g_B2lo[1024];   // [(s*4+nb)*32 + lane]

// ---------------------------------------------------------------------------
// SMEM layout (bytes), 256-thread block, 128 j rows:
//   A   : ef chunk bf16-pairs [128 j][20]  (16 kpairs + 4 pad) hi/lo
//   G   : gelu bf16-pairs     [128 j][68]  (64 hpairs + 4 pad) hi/lo
//   CST : C2 staging fp32     [128 j][37]
//   A aliases inside G-hi; CST aliases G-hi (all windows barrier-fenced)
// ---------------------------------------------------------------------------
#define GHIO   0         // 34816
#define GLOO   34816     // 34816 -> 69632
#define AHIO   0         // 10240 (inside G-hi, dead before G written)
#define ALOO   10240     // 10240 -> 20480
#define CSTO   0         // 18944 (over G-hi, after GEMM2)
#define TSOF   69632     // 512
#define KEEPO  70144     // 512
#define SPARTO 70656     // 2048 (256 x float2)
#define SMEM_TOTAL 72704

// ---------------------------------------------------------------------------
__device__ __forceinline__ uint32_t smem_u32(const void* p) {
    uint32_t a;
    asm("{ .reg .u64 t; cvta.to.shared.u64 t, %1; cvt.u32.u64 %0, t; }"
        : "=r"(a) : "l"(p));
    return a;
}

__device__ __forceinline__ void mma_bf16(float* c, uint32_t a0, uint32_t a1,
                                         uint32_t a2, uint32_t a3,
                                         uint32_t b0, uint32_t b1) {
    asm volatile(
        "mma.sync.aligned.m16n8k16.row.col.f32.bf16.bf16.f32 "
        "{%0,%1,%2,%3}, {%4,%5,%6,%7}, {%8,%9}, {%0,%1,%2,%3};"
        : "+f"(c[0]), "+f"(c[1]), "+f"(c[2]), "+f"(c[3])
        : "r"(a0), "r"(a1), "r"(a2), "r"(a3), "r"(b0), "r"(b1));
}

__device__ __forceinline__ void ldsm_x4(uint32_t& r0, uint32_t& r1,
                                        uint32_t& r2, uint32_t& r3,
                                        uint32_t addr) {
    asm volatile("ldmatrix.sync.aligned.m8n8.x4.shared.b16 {%0,%1,%2,%3}, [%4];"
                 : "=r"(r0), "=r"(r1), "=r"(r2), "=r"(r3) : "r"(addr));
}

// split e0,e1 into bf16 hi/lo pairs; packed reg = (elem k low 16, k+1 high)
__device__ __forceinline__ void splitpack(float e0, float e1,
                                          uint32_t& hi, uint32_t& lo) {
    __nv_bfloat16 h0 = __float2bfloat16_rn(e0);
    __nv_bfloat16 h1 = __float2bfloat16_rn(e1);
    float h0f = __bfloat162float(h0);
    float h1f = __bfloat162float(h1);
    __nv_bfloat16 l0 = __float2bfloat16_rn(e0 - h0f);
    __nv_bfloat16 l1 = __float2bfloat16_rn(e1 - h1f);
    hi = ((uint32_t)__bfloat16_as_ushort(h1) << 16) | __bfloat16_as_ushort(h0);
    lo = ((uint32_t)__bfloat16_as_ushort(l1) << 16) | __bfloat16_as_ushort(l0);
}

__device__ __forceinline__ float gelu_exact(float x) {
    return 0.5f * x * (1.0f + erff(x * 0.70710678118654752f));
}

// ---------------------------------------------------------------------------
__global__ void mask_kernel(const float* __restrict__ nf) {
    int bn = blockIdx.x;
    const float4* p = (const float4*)(nf + (size_t)bn * FD);
    int nz = 0;
    for (int q = threadIdx.x; q < FD / 4; q += blockDim.x) {
        float4 v = p[q];
        nz |= (v.x != 0.0f) | (v.y != 0.0f) | (v.z != 0.0f) | (v.w != 0.0f);
    }
    int any = __syncthreads_or(nz);
    if (threadIdx.x == 0) g_pad[bn] = (any == 0) ? 1 : 0;
}

// ---------------------------------------------------------------------------
// pack w1^T / w2^T into mma B-fragment order:
//   B1: for k-step s(0..7), n-block nb(0..15), lane l:
//       n = nb*8 + l/4, kp = s*8 + (l&3); b0 = pair(kp), b1 = pair(kp+4)
//   B2: same with nb(0..3), hp over hidden dim
// ---------------------------------------------------------------------------
__global__ void prep_kernel(const float* __restrict__ w1,
                            const float* __restrict__ w2) {
    int t = blockIdx.x * 256 + threadIdx.x;     // grid 16 x 256 = 4096
    {
        int idx = t;
        int s  = idx >> 9;
        int nb = (idx >> 5) & 15;
        int l  = idx & 31;
        int h  = nb * 8 + (l >> 2);
        int kp = s * 8 + (l & 3);
        float v0 = w1[(2 * kp) * 128 + h];
        float v1 = w1[(2 * kp + 1) * 128 + h];
        float v2 = w1[(2 * (kp + 4)) * 128 + h];
        float v3 = w1[(2 * (kp + 4) + 1) * 128 + h];
        uint32_t h0, l0, h1, l1;
        splitpack(v0, v1, h0, l0);
        splitpack(v2, v3, h1, l1);
        g_B1hi[idx] = make_uint2(h0, h1);
        g_B1lo[idx] = make_uint2(l0, l1);
    }
    if (t < 1024) {
        int idx = t;
        int s  = idx >> 7;
        int nb = (idx >> 5) & 3;
        int l  = idx & 31;
        int m  = nb * 8 + (l >> 2);
        int hp = s * 8 + (l & 3);
        float v0 = w2[(2 * hp) * 32 + m];
        float v1 = w2[(2 * hp + 1) * 32 + m];
        float v2 = w2[(2 * (hp + 4)) * 32 + m];
        float v3 = w2[(2 * (hp + 4) + 1) * 32 + m];
        uint32_t h0, l0, h1, l1;
        splitpack(v0, v1, h0, l0);
        splitpack(v2, v3, h1, l1);
        g_B2hi[idx] = make_uint2(h0, h1);
        g_B2lo[idx] = make_uint2(l0, l1);
    }
}

// ---------------------------------------------------------------------------
// main: one block per (i, b, jhalf); 256 threads; occupancy 2
// ---------------------------------------------------------------------------
__global__ __launch_bounds__(256, 2)
void main_kernel(const float* __restrict__ pos,
                 const float* __restrict__ means,
                 const float* __restrict__ betas,
                 const float* __restrict__ b1,
                 const float* __restrict__ b2,
                 float* __restrict__ gab,
                 float* __restrict__ dpos)
{
    extern __shared__ char smem[];
    const uint32_t sbase = smem_u32(smem);
    uint32_t* Ahi  = (uint32_t*)(smem + AHIO);
    uint32_t* Alo  = (uint32_t*)(smem + ALOO);
    uint32_t* Ghi  = (uint32_t*)(smem + GHIO);
    uint32_t* Glo  = (uint32_t*)(smem + GLOO);
    float*    Cst  = (float*)(smem + CSTO);
    float*    ts   = (float*)(smem + TSOF);
    float*    keep = (float*)(smem + KEEPO);
    float2*   spart = (float2*)(smem + SPARTO);

    const int i    = blockIdx.x;
    const int b    = blockIdx.y;
    const int jh   = blockIdx.z;
    const int tid  = threadIdx.x;
    const int w    = tid >> 5;          // 0..7
    const int lane = tid & 31;
    const int g    = lane >> 2;
    const int c4   = lane & 3;

    // ldmatrix per-lane address components (A / G operand pattern)
    const int lmat = lane >> 3, lrow = lane & 7;
    const int rowA = lrow + 8 * (lmat & 1);
    const int kaddA = (lmat >> 1) * 4;

    // ---- phase 0: dpos, t[jl], keep[jl] for this half's 128 rows ----
    const float pix = pos[(b * NN + i) * 3 + 0];
    const float piy = pos[(b * NN + i) * 3 + 1];
    const float piz = pos[(b * NN + i) * 3 + 2];
    if (tid < 128) {
        int jl = tid;
        int j  = jh * 128 + jl;
        float pjx = pos[(b * NN + j) * 3 + 0];
        float pjy = pos[(b * NN + j) * 3 + 1];
        float pjz = pos[(b * NN + j) * 3 + 2];
        float dx = pix - pjx, dy = piy - pjy, dz = piz - pjz;
        size_t dbase = (((size_t)(b * NN + i)) * NN + j) * 3;
        dpos[dbase + 0] = dx;
        dpos[dbase + 1] = dy;
        dpos[dbase + 2] = dz;
        float r = dx * dx + dy * dy + dz * dz;
        float d = (r > 0.0f) ? sqrtf(r) : 0.0f;
        ts[jl] = expf(-d);              // ALPHA=1, CUT_LO=0
        keep[jl] = g_pad[b * NN + j] ? 0.0f : 1.0f;
    }
    __syncthreads();

    // ================= GEMM1: C1[128j x 128h] = ef @ w1 ====================
    const int wj = w & 1;    // 64 rows at wj*64
    const int wh = w >> 1;   // 32 cols at wh*32
    const int gkp = tid & 15;
    const int gjg = tid >> 4;

    float acc[4][4][4];
#pragma unroll
    for (int mi = 0; mi < 4; mi++)
#pragma unroll
        for (int ni = 0; ni < 4; ni++)
#pragma unroll
            for (int q = 0; q < 4; q++) acc[mi][ni][q] = 0.0f;

    for (int kc = 0; kc < 4; kc++) {
        // ---- generate A chunk [128 j][32 k] + masked partial sums ----
        {
            int k0 = kc * 32 + 2 * gkp;
            float mk0 = means[k0], mk1 = means[k0 + 1];
            float bk0 = betas[k0], bk1 = betas[k0 + 1];
            float s0 = 0.0f, s1 = 0.0f;
#pragma unroll
            for (int q = 0; q < 8; q++) {
                int jl = gjg * 8 + q;
                float t  = ts[jl];
                float kj = keep[jl];
                float d0 = t - mk0, d1 = t - mk1;
                float e0 = expf(-bk0 * d0 * d0);
                float e1 = expf(-bk1 * d1 * d1);
                s0 += e0 * kj;  s1 += e1 * kj;
                uint32_t hi, lo;
                splitpack(e0, e1, hi, lo);
                Ahi[jl * 20 + gkp] = hi;
                Alo[jl * 20 + gkp] = lo;
            }
            spart[tid] = make_float2(s0, s1);
        }
        __syncthreads();

        // ---- fold this half's masked j-sums (warp 0; overlaps MMA) ----
        if (tid < 32) {
            int kp = tid >> 1, c = tid & 1;
            float s = 0.0f;
#pragma unroll
            for (int jg = 0; jg < 16; jg++) {
                float2 v = spart[jg * 16 + kp];
                s += c ? v.y : v.x;
            }
            g_sumef2[(size_t)jh * (BB * NN * KK)
                     + ((size_t)(b * NN + i)) * 128 + kc * 32 + tid] = s;
        }

        // ---- MMA: 2 k-steps of 16; B frags streamed from L2 ----
#pragma unroll
        for (int ks = 0; ks < 2; ks++) {
            int s = kc * 2 + ks;
            uint2 bh[4], bl[4];
#pragma unroll
            for (int ni = 0; ni < 4; ni++) {
                int idx = ((s * 16 + wh * 4 + ni) * 32) + lane;
                bh[ni] = g_B1hi[idx];
                bl[ni] = g_B1lo[idx];
            }
            int kloc = ks * 8;
#pragma unroll
            for (int mi = 0; mi < 4; mi++) {
                uint32_t aoff = (uint32_t)(((wj * 64 + mi * 16 + rowA) * 20
                                            + kloc + kaddA) * 4);
                uint32_t ah0, ah1, ah2, ah3, al0, al1, al2, al3;
                ldsm_x4(ah0, ah1, ah2, ah3, sbase + AHIO + aoff);
                ldsm_x4(al0, al1, al2, al3, sbase + ALOO + aoff);
#pragma unroll
                for (int ni = 0; ni < 4; ni++) {
                    mma_bf16(acc[mi][ni], ah0, ah1, ah2, ah3, bh[ni].x, bh[ni].y);
                    mma_bf16(acc[mi][ni], al0, al1, al2, al3, bh[ni].x, bh[ni].y);
                    mma_bf16(acc[mi][ni], ah0, ah1, ah2, ah3, bl[ni].x, bl[ni].y);
                }
            }
        }
        __syncthreads();   // A consumed; next gen may overwrite
    }

    // ---- epilogue1: +b1, exact GELU, split/pack into G (aliases A) ----
    {
        float b1r0[4], b1r1[4];
#pragma unroll
        for (int ni = 0; ni < 4; ni++) {
            int h0 = wh * 32 + ni * 8 + c4 * 2;
            b1r0[ni] = b1[h0];
            b1r1[ni] = b1[h0 + 1];
        }
#pragma unroll
        for (int mi = 0; mi < 4; mi++) {
            int r0 = wj * 64 + mi * 16 + g;
            int r1 = r0 + 8;
#pragma unroll
            for (int ni = 0; ni < 4; ni++) {
                int hp = wh * 16 + ni * 4 + c4;
                float g00 = gelu_exact(acc[mi][ni][0] + b1r0[ni]);
                float g01 = gelu_exact(acc[mi][ni][1] + b1r1[ni]);
                float g10 = gelu_exact(acc[mi][ni][2] + b1r0[ni]);
                float g11 = gelu_exact(acc[mi][ni][3] + b1r1[ni]);
                uint32_t hi, lo;
                splitpack(g00, g01, hi, lo);
                Ghi[r0 * 68 + hp] = hi;  Glo[r0 * 68 + hp] = lo;
                splitpack(g10, g11, hi, lo);
                Ghi[r1 * 68 + hp] = hi;  Glo[r1 * 68 + hp] = lo;
            }
        }
    }
    __syncthreads();

    // ================= GEMM2: C2[128j x 32m] = G @ w2 ======================
    float acc2[4][4];
#pragma unroll
    for (int ni = 0; ni < 4; ni++)
#pragma unroll
        for (int q = 0; q < 4; q++) acc2[ni][q] = 0.0f;

    const int jt = w * 16;
#pragma unroll
    for (int s = 0; s < 8; s++) {
        uint32_t goff = (uint32_t)(((jt + rowA) * 68 + s * 8 + kaddA) * 4);
        uint32_t gh0, gh1, gh2, gh3, gl0, gl1, gl2, gl3;
        ldsm_x4(gh0, gh1, gh2, gh3, sbase + GHIO + goff);
        ldsm_x4(gl0, gl1, gl2, gl3, sbase + GLOO + goff);
        uint2 bh[4], bl[4];
#pragma unroll
        for (int ni = 0; ni < 4; ni++) {
            int idx = ((s * 4 + ni) * 32) + lane;
            bh[ni] = g_B2hi[idx];
            bl[ni] = g_B2lo[idx];
        }
#pragma unroll
        for (int ni = 0; ni < 4; ni++) {
            mma_bf16(acc2[ni], gh0, gh1, gh2, gh3, bh[ni].x, bh[ni].y);
            mma_bf16(acc2[ni], gl0, gl1, gl2, gl3, bh[ni].x, bh[ni].y);
            mma_bf16(acc2[ni], gh0, gh1, gh2, gh3, bl[ni].x, bl[ni].y);
        }
    }
    __syncthreads();   // G consumed; Cst may alias

    // ---- epilogue2: +b2 into staging ----
#pragma unroll
    for (int ni = 0; ni < 4; ni++) {
        int m0 = ni * 8 + c4 * 2;
        float e0 = b2[m0], e1 = b2[m0 + 1];
        int r0 = jt + g, r1 = r0 + 8;
        Cst[r0 * 37 + m0]     = acc2[ni][0] + e0;
        Cst[r0 * 37 + m0 + 1] = acc2[ni][1] + e1;
        Cst[r1 * 37 + m0]     = acc2[ni][2] + e0;
        Cst[r1 * 37 + m0 + 1] = acc2[ni][3] + e1;
    }
    __syncthreads();

    // ---- coalesced gab stores: gab[b][m][i][jh*128 + jl] ----
    {
#pragma unroll
        for (int it = 0; it < 16; it++) {
            int idx = it * 256 + tid;
            int m  = idx >> 7;
            int jl = idx & 127;
            int j  = jh * 128 + jl;
            float v = Cst[jl * 37 + m];
            gab[(((size_t)(b * HH + m)) * NN + i) * NN + j] =
                (keep[jl] == 0.0f) ? -1e20f : v;
        }
    }
}

// ---------------------------------------------------------------------------
// merge_edge_features = (sum over both halves) @ ew + eb
// grid (128 row-tiles, 3 col-chunks); each thread: 1 col x 16 rows
// ---------------------------------------------------------------------------
__global__ __launch_bounds__(256)
void merge_kernel(const float* __restrict__ ew,
                  const float* __restrict__ eb,
                  float* __restrict__ out)
{
    __shared__ float sef[16 * 128];
    const int r0  = blockIdx.x * 16;
    const int col = blockIdx.y * 256 + threadIdx.x;
    const int tid = threadIdx.x;

#pragma unroll
    for (int q = 0; q < 8; q++) {
        size_t off = (size_t)r0 * 128 + tid + 256 * q;
        sef[tid + 256 * q] = g_sumef2[off] + g_sumef2[(size_t)(BB*NN*KK) + off];
    }
    __syncthreads();

    float acc[16];
    {
        float e = eb[col];
#pragma unroll
        for (int r = 0; r < 16; r++) acc[r] = e;
    }

#pragma unroll 4
    for (int k = 0; k < 128; k++) {
        float v = ew[(size_t)k * EMB + col];
#pragma unroll
        for (int r = 0; r < 16; r++)
            acc[r] = fmaf(sef[r * 128 + k], v, acc[r]);
    }

#pragma unroll
    for (int r = 0; r < 16; r++)
        out[(size_t)(r0 + r) * EMB + col] = acc[r];
}

// ---------------------------------------------------------------------------
extern "C" void kernel_launch(void* const* d_in, const int* in_sizes, int n_in,
                              void* d_out, int out_size) {
    const float* nf    = (const float*)d_in[0];
    const float* pos   = (const float*)d_in[1];
    const float* means = (const float*)d_in[2];
    const float* betas = (const float*)d_in[3];
    const float* w1    = (const float*)d_in[4];
    const float* b1    = (const float*)d_in[5];
    const float* w2    = (const float*)d_in[6];
    const float* b2    = (const float*)d_in[7];
    const float* ew    = (const float*)d_in[8];
    const float* eb    = (const float*)d_in[9];

    float* out  = (float*)d_out;
    float* gab  = out;
    float* mef  = out + GAB_ELEMS;
    float* dpos = out + GAB_ELEMS + MEF_ELEMS;

    cudaFuncSetAttribute(main_kernel,
                         cudaFuncAttributeMaxDynamicSharedMemorySize,
                         SMEM_TOTAL);

    prep_kernel<<<16, 256>>>(w1, w2);
    mask_kernel<<<BB * NN, 128>>>(nf);

    dim3 grid(NN, BB, 2);
    main_kernel<<<grid, 256, SMEM_TOTAL>>>(
        pos, means, betas, b1, b2, gab, dpos);

    dim3 mgrid((BB * NN) / 16, 3);
    merge_kernel<<<mgrid, 256>>>(ew, eb, mef);
}

// round 13
// speedup vs baseline: 1.6872x; 1.2633x over previous
#include <cuda_runtime.h>
#include <cuda_bf16.h>
#include <math.h>
#include <stdint.h>

#define BB 8
#define NN 256
#define KK 128
#define HH 32
#define EMB 768
#define FD 768

#define GAB_ELEMS   (BB*HH*NN*NN)      // 16777216
#define MEF_ELEMS   (BB*NN*EMB)        // 1572864

// scratch (no cudaMalloc allowed)
__device__ float g_sumef2[2 * BB * NN * KK];   // [jh][b*N+i][k]
__device__ int   g_pad[BB * NN];
// pre-packed mma B-fragments (bf16 hi/lo pairs), exact lane order
__device__ uint2 g_B1hi[4096], g_B1lo[4096];   // [(s*16+nb)*32 + lane]
__device__ uint2 g_B2hi[1024], g_B2lo[1024];   // [(s*4+nb)*32 + lane]

// ---------------------------------------------------------------------------
// SMEM layout (bytes), 256-thread block, 128 j rows (see R10 notes)
// ---------------------------------------------------------------------------
#define GHIO   0         // 34816
#define GLOO   34816     // 34816 -> 69632
#define AHIO   0         // 10240 (inside G-hi, dead before G written)
#define ALOO   10240     // 10240 -> 20480
#define CSTO   0         // 18944 (over G-hi, after GEMM2)
#define TSOF   69632     // 512
#define KEEPO  70144     // 512
#define SPARTO 70656     // 2048 (256 x float2)
#define SMEM_TOTAL 72704

// ---------------------------------------------------------------------------
__device__ __forceinline__ uint32_t smem_u32(const void* p) {
    uint32_t a;
    asm("{ .reg .u64 t; cvta.to.shared.u64 t, %1; cvt.u32.u64 %0, t; }"
        : "=r"(a) : "l"(p));
    return a;
}

__device__ __forceinline__ void mma_bf16(float* c, uint32_t a0, uint32_t a1,
                                         uint32_t a2, uint32_t a3,
                                         uint32_t b0, uint32_t b1) {
    asm volatile(
        "mma.sync.aligned.m16n8k16.row.col.f32.bf16.bf16.f32 "
        "{%0,%1,%2,%3}, {%4,%5,%6,%7}, {%8,%9}, {%0,%1,%2,%3};"
        : "+f"(c[0]), "+f"(c[1]), "+f"(c[2]), "+f"(c[3])
        : "r"(a0), "r"(a1), "r"(a2), "r"(a3), "r"(b0), "r"(b1));
}

__device__ __forceinline__ void ldsm_x4(uint32_t& r0, uint32_t& r1,
                                        uint32_t& r2, uint32_t& r3,
                                        uint32_t addr) {
    asm volatile("ldmatrix.sync.aligned.m8n8.x4.shared.b16 {%0,%1,%2,%3}, [%4];"
                 : "=r"(r0), "=r"(r1), "=r"(r2), "=r"(r3) : "r"(addr));
}

// precise split (round-to-nearest hi) - used in prep only
__device__ __forceinline__ void splitpack(float e0, float e1,
                                          uint32_t& hi, uint32_t& lo) {
    __nv_bfloat16 h0 = __float2bfloat16_rn(e0);
    __nv_bfloat16 h1 = __float2bfloat16_rn(e1);
    float h0f = __bfloat162float(h0);
    float h1f = __bfloat162float(h1);
    __nv_bfloat16 l0 = __float2bfloat16_rn(e0 - h0f);
    __nv_bfloat16 l1 = __float2bfloat16_rn(e1 - h1f);
    hi = ((uint32_t)__bfloat16_as_ushort(h1) << 16) | __bfloat16_as_ushort(h0);
    lo = ((uint32_t)__bfloat16_as_ushort(l1) << 16) | __bfloat16_as_ushort(l0);
}

// fast truncation split: hi = trunc16(e) exact, lo = trunc16(e - hi)
// total representation error <= 2^-16 |e|
__device__ __forceinline__ void splitpack_fast(float e0, float e1,
                                               uint32_t& hi, uint32_t& lo) {
    uint32_t b0 = __float_as_uint(e0), b1 = __float_as_uint(e1);
    hi = __byte_perm(b0, b1, 0x7632);
    float l0f = e0 - __uint_as_float(b0 & 0xffff0000u);
    float l1f = e1 - __uint_as_float(b1 & 0xffff0000u);
    lo = __byte_perm(__float_as_uint(l0f), __float_as_uint(l1f), 0x7632);
}

// tanh-approx GELU with HW tanh (inputs here are small, |x| << 1)
__device__ __forceinline__ float gelu_fast(float x) {
    float u = x * fmaf(0.0356774081f, x * x, 0.7978845608f);
    float t;
    asm("tanh.approx.f32 %0, %1;" : "=f"(t) : "f"(u));
    return 0.5f * x * (1.0f + t);
}

// ---------------------------------------------------------------------------
__global__ void mask_kernel(const float* __restrict__ nf) {
    int bn = blockIdx.x;
    const float4* p = (const float4*)(nf + (size_t)bn * FD);
    int nz = 0;
    for (int q = threadIdx.x; q < FD / 4; q += blockDim.x) {
        float4 v = p[q];
        nz |= (v.x != 0.0f) | (v.y != 0.0f) | (v.z != 0.0f) | (v.w != 0.0f);
    }
    int any = __syncthreads_or(nz);
    if (threadIdx.x == 0) g_pad[bn] = (any == 0) ? 1 : 0;
}

// ---------------------------------------------------------------------------
// pack w1^T / w2^T into mma B-fragment order (precise rn split; runs once)
// ---------------------------------------------------------------------------
__global__ void prep_kernel(const float* __restrict__ w1,
                            const float* __restrict__ w2) {
    int t = blockIdx.x * 256 + threadIdx.x;     // grid 16 x 256 = 4096
    {
        int idx = t;
        int s  = idx >> 9;
        int nb = (idx >> 5) & 15;
        int l  = idx & 31;
        int h  = nb * 8 + (l >> 2);
        int kp = s * 8 + (l & 3);
        float v0 = w1[(2 * kp) * 128 + h];
        float v1 = w1[(2 * kp + 1) * 128 + h];
        float v2 = w1[(2 * (kp + 4)) * 128 + h];
        float v3 = w1[(2 * (kp + 4) + 1) * 128 + h];
        uint32_t h0, l0, h1, l1;
        splitpack(v0, v1, h0, l0);
        splitpack(v2, v3, h1, l1);
        g_B1hi[idx] = make_uint2(h0, h1);
        g_B1lo[idx] = make_uint2(l0, l1);
    }
    if (t < 1024) {
        int idx = t;
        int s  = idx >> 7;
        int nb = (idx >> 5) & 3;
        int l  = idx & 31;
        int m  = nb * 8 + (l >> 2);
        int hp = s * 8 + (l & 3);
        float v0 = w2[(2 * hp) * 32 + m];
        float v1 = w2[(2 * hp + 1) * 32 + m];
        float v2 = w2[(2 * (hp + 4)) * 32 + m];
        float v3 = w2[(2 * (hp + 4) + 1) * 32 + m];
        uint32_t h0, l0, h1, l1;
        splitpack(v0, v1, h0, l0);
        splitpack(v2, v3, h1, l1);
        g_B2hi[idx] = make_uint2(h0, h1);
        g_B2lo[idx] = make_uint2(l0, l1);
    }
}

// ---------------------------------------------------------------------------
// main: one block per (i, b, jhalf); 256 threads; occupancy 2
// ---------------------------------------------------------------------------
__global__ __launch_bounds__(256, 2)
void main_kernel(const float* __restrict__ pos,
                 const float* __restrict__ means,
                 const float* __restrict__ betas,
                 const float* __restrict__ b1,
                 const float* __restrict__ b2,
                 float* __restrict__ gab,
                 float* __restrict__ dpos)
{
    extern __shared__ char smem[];
    const uint32_t sbase = smem_u32(smem);
    uint32_t* Ahi  = (uint32_t*)(smem + AHIO);
    uint32_t* Alo  = (uint32_t*)(smem + ALOO);
    uint32_t* Ghi  = (uint32_t*)(smem + GHIO);
    uint32_t* Glo  = (uint32_t*)(smem + GLOO);
    float*    Cst  = (float*)(smem + CSTO);
    float*    ts   = (float*)(smem + TSOF);
    float*    keep = (float*)(smem + KEEPO);
    float2*   spart = (float2*)(smem + SPARTO);

    const int i    = blockIdx.x;
    const int b    = blockIdx.y;
    const int jh   = blockIdx.z;
    const int tid  = threadIdx.x;
    const int w    = tid >> 5;          // 0..7
    const int lane = tid & 31;
    const int g    = lane >> 2;
    const int c4   = lane & 3;

    // ldmatrix per-lane address components (A / G operand pattern)
    const int lmat = lane >> 3, lrow = lane & 7;
    const int rowA = lrow + 8 * (lmat & 1);
    const int kaddA = (lmat >> 1) * 4;

    // ---- phase 0: dpos, t[jl], keep[jl] for this half's 128 rows ----
    const float pix = pos[(b * NN + i) * 3 + 0];
    const float piy = pos[(b * NN + i) * 3 + 1];
    const float piz = pos[(b * NN + i) * 3 + 2];
    if (tid < 128) {
        int jl = tid;
        int j  = jh * 128 + jl;
        float pjx = pos[(b * NN + j) * 3 + 0];
        float pjy = pos[(b * NN + j) * 3 + 1];
        float pjz = pos[(b * NN + j) * 3 + 2];
        float dx = pix - pjx, dy = piy - pjy, dz = piz - pjz;
        size_t dbase = (((size_t)(b * NN + i)) * NN + j) * 3;
        dpos[dbase + 0] = dx;
        dpos[dbase + 1] = dy;
        dpos[dbase + 2] = dz;
        float r = dx * dx + dy * dy + dz * dz;
        float d = (r > 0.0f) ? sqrtf(r) : 0.0f;
        ts[jl] = expf(-d);              // precise (beta-amplified sensitivity)
        keep[jl] = g_pad[b * NN + j] ? 0.0f : 1.0f;
    }
    __syncthreads();

    // ================= GEMM1: C1[128j x 128h] = ef @ w1 ====================
    const int wj = w & 1;    // 64 rows at wj*64
    const int wh = w >> 1;   // 32 cols at wh*32
    const int gkp = tid & 15;
    const int gjg = tid >> 4;

    float acc[4][4][4];
#pragma unroll
    for (int mi = 0; mi < 4; mi++)
#pragma unroll
        for (int ni = 0; ni < 4; ni++)
#pragma unroll
            for (int q = 0; q < 4; q++) acc[mi][ni][q] = 0.0f;

    for (int kc = 0; kc < 4; kc++) {
        // ---- generate A chunk [128 j][32 k] + masked partial sums ----
        {
            int k0 = kc * 32 + 2 * gkp;
            float mk0 = means[k0], mk1 = means[k0 + 1];
            float bk0 = betas[k0], bk1 = betas[k0 + 1];
            float s0 = 0.0f, s1 = 0.0f;
#pragma unroll
            for (int q = 0; q < 8; q++) {
                int jl = gjg * 8 + q;
                float t  = ts[jl];
                float kj = keep[jl];
                float d0 = t - mk0, d1 = t - mk1;
                float e0 = __expf(-bk0 * d0 * d0);
                float e1 = __expf(-bk1 * d1 * d1);
                s0 += e0 * kj;  s1 += e1 * kj;
                uint32_t hi, lo;
                splitpack_fast(e0, e1, hi, lo);
                Ahi[jl * 20 + gkp] = hi;
                Alo[jl * 20 + gkp] = lo;
            }
            spart[tid] = make_float2(s0, s1);
        }
        __syncthreads();

        // ---- fold this half's masked j-sums (warp 0; overlaps MMA) ----
        if (tid < 32) {
            int kp = tid >> 1, c = tid & 1;
            float s = 0.0f;
#pragma unroll
            for (int jg = 0; jg < 16; jg++) {
                float2 v = spart[jg * 16 + kp];
                s += c ? v.y : v.x;
            }
            g_sumef2[(size_t)jh * (BB * NN * KK)
                     + ((size_t)(b * NN + i)) * 128 + kc * 32 + tid] = s;
        }

        // ---- MMA: 2 k-steps of 16; B frags streamed from L2 ----
#pragma unroll
        for (int ks = 0; ks < 2; ks++) {
            int s = kc * 2 + ks;
            uint2 bh[4], bl[4];
#pragma unroll
            for (int ni = 0; ni < 4; ni++) {
                int idx = ((s * 16 + wh * 4 + ni) * 32) + lane;
                bh[ni] = g_B1hi[idx];
                bl[ni] = g_B1lo[idx];
            }
            int kloc = ks * 8;
#pragma unroll
            for (int mi = 0; mi < 4; mi++) {
                uint32_t aoff = (uint32_t)(((wj * 64 + mi * 16 + rowA) * 20
                                            + kloc + kaddA) * 4);
                uint32_t ah0, ah1, ah2, ah3, al0, al1, al2, al3;
                ldsm_x4(ah0, ah1, ah2, ah3, sbase + AHIO + aoff);
                ldsm_x4(al0, al1, al2, al3, sbase + ALOO + aoff);
#pragma unroll
                for (int ni = 0; ni < 4; ni++) {
                    mma_bf16(acc[mi][ni], ah0, ah1, ah2, ah3, bh[ni].x, bh[ni].y);
                    mma_bf16(acc[mi][ni], al0, al1, al2, al3, bh[ni].x, bh[ni].y);
                    mma_bf16(acc[mi][ni], ah0, ah1, ah2, ah3, bl[ni].x, bl[ni].y);
                }
            }
        }
        __syncthreads();   // A consumed; next gen may overwrite
    }

    // ---- epilogue1: +b1, fast GELU, split/pack into G (aliases A) ----
    {
        float b1r0[4], b1r1[4];
#pragma unroll
        for (int ni = 0; ni < 4; ni++) {
            int h0 = wh * 32 + ni * 8 + c4 * 2;
            b1r0[ni] = b1[h0];
            b1r1[ni] = b1[h0 + 1];
        }
#pragma unroll
        for (int mi = 0; mi < 4; mi++) {
            int r0 = wj * 64 + mi * 16 + g;
            int r1 = r0 + 8;
#pragma unroll
            for (int ni = 0; ni < 4; ni++) {
                int hp = wh * 16 + ni * 4 + c4;
                float g00 = gelu_fast(acc[mi][ni][0] + b1r0[ni]);
                float g01 = gelu_fast(acc[mi][ni][1] + b1r1[ni]);
                float g10 = gelu_fast(acc[mi][ni][2] + b1r0[ni]);
                float g11 = gelu_fast(acc[mi][ni][3] + b1r1[ni]);
                uint32_t hi, lo;
                splitpack_fast(g00, g01, hi, lo);
                Ghi[r0 * 68 + hp] = hi;  Glo[r0 * 68 + hp] = lo;
                splitpack_fast(g10, g11, hi, lo);
                Ghi[r1 * 68 + hp] = hi;  Glo[r1 * 68 + hp] = lo;
            }
        }
    }
    __syncthreads();

    // ================= GEMM2: C2[128j x 32m] = G @ w2 ======================
    float acc2[4][4];
#pragma unroll
    for (int ni = 0; ni < 4; ni++)
#pragma unroll
        for (int q = 0; q < 4; q++) acc2[ni][q] = 0.0f;

    const int jt = w * 16;
#pragma unroll
    for (int s = 0; s < 8; s++) {
        uint32_t goff = (uint32_t)(((jt + rowA) * 68 + s * 8 + kaddA) * 4);
        uint32_t gh0, gh1, gh2, gh3, gl0, gl1, gl2, gl3;
        ldsm_x4(gh0, gh1, gh2, gh3, sbase + GHIO + goff);
        ldsm_x4(gl0, gl1, gl2, gl3, sbase + GLOO + goff);
        uint2 bh[4], bl[4];
#pragma unroll
        for (int ni = 0; ni < 4; ni++) {
            int idx = ((s * 4 + ni) * 32) + lane;
            bh[ni] = g_B2hi[idx];
            bl[ni] = g_B2lo[idx];
        }
#pragma unroll
        for (int ni = 0; ni < 4; ni++) {
            mma_bf16(acc2[ni], gh0, gh1, gh2, gh3, bh[ni].x, bh[ni].y);
            mma_bf16(acc2[ni], gl0, gl1, gl2, gl3, bh[ni].x, bh[ni].y);
            mma_bf16(acc2[ni], gh0, gh1, gh2, gh3, bl[ni].x, bl[ni].y);
        }
    }
    __syncthreads();   // G consumed; Cst may alias

    // ---- epilogue2: +b2 into staging ----
#pragma unroll
    for (int ni = 0; ni < 4; ni++) {
        int m0 = ni * 8 + c4 * 2;
        float e0 = b2[m0], e1 = b2[m0 + 1];
        int r0 = jt + g, r1 = r0 + 8;
        Cst[r0 * 37 + m0]     = acc2[ni][0] + e0;
        Cst[r0 * 37 + m0 + 1] = acc2[ni][1] + e1;
        Cst[r1 * 37 + m0]     = acc2[ni][2] + e0;
        Cst[r1 * 37 + m0 + 1] = acc2[ni][3] + e1;
    }
    __syncthreads();

    // ---- coalesced gab stores: gab[b][m][i][jh*128 + jl] ----
    {
#pragma unroll
        for (int it = 0; it < 16; it++) {
            int idx = it * 256 + tid;
            int m  = idx >> 7;
            int jl = idx & 127;
            int j  = jh * 128 + jl;
            float v = Cst[jl * 37 + m];
            gab[(((size_t)(b * HH + m)) * NN + i) * NN + j] =
                (keep[jl] == 0.0f) ? -1e20f : v;
        }
    }
}

// ---------------------------------------------------------------------------
// merge_edge_features = (sum over both halves) @ ew + eb
// grid (128 row-tiles, 3 col-chunks); thread: 1 col x 16 rows; float4 sef
// ---------------------------------------------------------------------------
__global__ __launch_bounds__(256)
void merge_kernel(const float* __restrict__ ew,
                  const float* __restrict__ eb,
                  float* __restrict__ out)
{
    __shared__ float sef[16 * 128];
    const int r0  = blockIdx.x * 16;
    const int col = blockIdx.y * 256 + threadIdx.x;
    const int tid = threadIdx.x;

#pragma unroll
    for (int q = 0; q < 8; q++) {
        size_t off = (size_t)r0 * 128 + tid + 256 * q;
        sef[tid + 256 * q] = g_sumef2[off] + g_sumef2[(size_t)(BB*NN*KK) + off];
    }
    __syncthreads();

    float acc[16];
    {
        float e = eb[col];
#pragma unroll
        for (int r = 0; r < 16; r++) acc[r] = e;
    }

    const float4* sef4 = (const float4*)sef;
#pragma unroll 2
    for (int k4 = 0; k4 < 32; k4++) {
        int k = k4 * 4;
        float v0 = ew[(size_t)(k + 0) * EMB + col];
        float v1 = ew[(size_t)(k + 1) * EMB + col];
        float v2 = ew[(size_t)(k + 2) * EMB + col];
        float v3 = ew[(size_t)(k + 3) * EMB + col];
#pragma unroll
        for (int r = 0; r < 16; r++) {
            float4 s = sef4[r * 32 + k4];
            acc[r] = fmaf(s.x, v0, acc[r]);
            acc[r] = fmaf(s.y, v1, acc[r]);
            acc[r] = fmaf(s.z, v2, acc[r]);
            acc[r] = fmaf(s.w, v3, acc[r]);
        }
    }

#pragma unroll
    for (int r = 0; r < 16; r++)
        out[(size_t)(r0 + r) * EMB + col] = acc[r];
}

// ---------------------------------------------------------------------------
extern "C" void kernel_launch(void* const* d_in, const int* in_sizes, int n_in,
                              void* d_out, int out_size) {
    const float* nf    = (const float*)d_in[0];
    const float* pos   = (const float*)d_in[1];
    const float* means = (const float*)d_in[2];
    const float* betas = (const float*)d_in[3];
    const float* w1    = (const float*)d_in[4];
    const float* b1    = (const float*)d_in[5];
    const float* w2    = (const float*)d_in[6];
    const float* b2    = (const float*)d_in[7];
    const float* ew    = (const float*)d_in[8];
    const float* eb    = (const float*)d_in[9];

    float* out  = (float*)d_out;
    float* gab  = out;
    float* mef  = out + GAB_ELEMS;
    float* dpos = out + GAB_ELEMS + MEF_ELEMS;

    cudaFuncSetAttribute(main_kernel,
                         cudaFuncAttributeMaxDynamicSharedMemorySize,
                         SMEM_TOTAL);

    prep_kernel<<<16, 256>>>(w1, w2);
    mask_kernel<<<BB * NN, 128>>>(nf);

    dim3 grid(NN, BB, 2);
    main_kernel<<<grid, 256, SMEM_TOTAL>>>(
        pos, means, betas, b1, b2, gab, dpos);

    dim3 mgrid((BB * NN) / 16, 3);
    merge_kernel<<<mgrid, 256>>>(ew, eb, mef);
}